// round 8
// baseline (speedup 1.0000x reference)
#include <cuda_runtime.h>
#include <cstdint>
#include <math.h>

// SoftPolygon B=32, P=32, 128x128.  out[b,y,x] = sigmoid(min_seg_sq * io)
//
// v8: v6 layout (warp = row-half, 2 px/lane, 8192 warps, warp-local precompute)
//     with all block-level coupling removed:
//     - vertices via per-lane LDG.64 + SHFL (no smem staging, NO __syncthreads)
//     - FFMA.SAT direct-dot distance (5 ops + min per pixel-edge)
//     - fast reciprocal for 1/sq_len (distance path is continuous; parity
//       division stays exact __fdiv_rn in reference op order)
//
// Numerical contract: parity bit-identical to reference via integer-threshold
// + XOR-mask; distance path continuous => ~1e-7 relative error only.

namespace {

constexpr int NB  = 32;
constexpr int NP  = 32;
constexpr int NH  = 128;
constexpr int NW  = 128;
constexpr int RPB = 2;          // rows per block (2 warps per row, 4 warps)

__global__ __launch_bounds__(128) void soft_poly_kernel(
    const float* __restrict__ verts,   // (B, P, 2)
    float* __restrict__ out)           // (B, H, W)
{
    const int b    = blockIdx.y;
    const int row0 = blockIdx.x * RPB;
    const int tid  = threadIdx.x;
    const int w    = tid >> 5;         // warp 0..3
    const int lane = tid & 31;
    const int r    = w >> 1;           // local row 0..1
    const int hp   = w & 1;            // column half 0..1
    const int row  = row0 + r;
    const float gy = (float)row;

    __shared__ float4 sC[4][NP];       // per-warp: {A, B, dx, x1}
    __shared__ float2 sD[4][NP];       // per-warp: {-dy, ys1}

    // ---- per-(row, edge) precompute; edge = lane; warp-local, no barriers ----
    unsigned int pmA, pmB;   // parity words for this warp's 2 column groups
    {
        // lane i loads vertex i; neighbors via shfl
        const float2 v = ((const float2*)verts)[b * NP + lane];
        const float fx = v.x, fy = v.y;
        const unsigned full = 0xffffffffu;
        const float tx = __shfl_sync(full, fx, (lane + 31) & 31);  // prev
        const float ty = __shfl_sync(full, fy, (lane + 31) & 31);
        const float x2 = __shfl_sync(full, fx, (lane + 1) & 31);   // next
        const float y2 = __shfl_sync(full, fy, (lane + 1) & 31);

        // crossing threshold, EXACT reference op order (mul, div, add)
        const bool cond = (fy > gy) != (ty > gy);
        float xint = __fadd_rn(
            __fdiv_rn(__fmul_rn(tx - fx, gy - fy), ty - fy), fx);
        if (!cond) xint = -1.0f;
        // #columns c in [0,128) with (float)c < xint — exact
        const float xc = fminf(fmaxf(ceilf(xint), 0.0f), 128.0f);
        const int ci = (int)xc - hp * 64;   // relative to this warp's half

        const int nA = min(max(ci,      0), 32);
        const int nB = min(max(ci - 32, 0), 32);
        const unsigned int mA = (unsigned int)((1ull << nA) - 1ull);
        const unsigned int mB = (unsigned int)((1ull << nB) - 1ull);
        pmA = __reduce_xor_sync(full, mA);
        pmB = __reduce_xor_sync(full, mB);

        // segment-distance constants for edge (v_i -> v_{i+1})
        const float dx = x2 - fx, dy = y2 - fy;
        const float sq  = dx * dx + dy * dy + 1e-5f;
        const float inv = __fdividef(1.0f, sq);   // continuous path: fast rcp OK
        const float ys1 = gy - fy;
        const float A = dx * inv;
        const float B = (ys1 * dy - fx * dx) * inv;   // dot = gx*A + B
        sC[w][lane] = make_float4(A, B, dx, fx);
        sD[w][lane] = make_float2(-dy, ys1);
    }
    __syncwarp();   // sC/sD written and read by the same warp only

    // ---- mainloop: 2 pixels per lane, 32 edges ----
    const float gx0 = (float)(hp * 64 + lane);
    const float gx1 = gx0 + 32.0f;
    float mn0 = 3.402823466e38f, mn1 = mn0;

#pragma unroll
    for (int i = 0; i < NP; ++i) {
        const float4 a  = sC[w][i];
        const float2 bd = sD[w][i];

#define PIX(GX, MN) do {                                     \
        const float t   = __saturatef(fmaf((GX), a.x, a.y)); \
        const float px  = fmaf(t, a.z, a.w);                 \
        const float xp  = (GX) - px;                         \
        const float yp  = fmaf(t, bd.x, bd.y);               \
        const float d   = fmaf(xp, xp, yp * yp);             \
        (MN) = fminf((MN), d);                               \
    } while (0)

        PIX(gx0, mn0);
        PIX(gx1, mn1);
#undef PIX
    }

    // ---- epilogue: sign from parity, sigmoid, store ----
    float* op = out + ((size_t)b * NH + row) * NW + hp * 64 + lane;
    {
        const float io0 = ((pmA >> lane) & 1u) ? 1.0f : -1.0f;
        const float io1 = ((pmB >> lane) & 1u) ? 1.0f : -1.0f;
        const float v0  = mn0 * io0;
        const float v1  = mn1 * io1;
        op[0]  = __fdividef(1.0f, 1.0f + __expf(-v0));
        op[32] = __fdividef(1.0f, 1.0f + __expf(-v1));
    }
}

}  // namespace

extern "C" void kernel_launch(void* const* d_in, const int* in_sizes, int n_in,
                              void* d_out, int out_size) {
    const float* verts = (const float*)d_in[0];
    float* out = (float*)d_out;
    dim3 grid(NH / RPB, NB);   // 64 x 32 = 2048 blocks, 4 warps each
    soft_poly_kernel<<<grid, 128>>>(verts, out);
}

// round 9
// speedup vs baseline: 1.0891x; 1.0891x over previous
#include <cuda_runtime.h>
#include <cstdint>
#include <math.h>

// SoftPolygon B=32, P=32, 128x128.  out[b,y,x] = sigmoid(min_seg_sq * io)
//
// v9: v6 (best: 9.34us kernel) with latency-exposure fixes only:
//     - min reduction split into even/odd-edge accumulators (halves the
//       serial FMNMX chain, doubles ILP)
//     - software-pipelined LDS of edge constants (next-iter prefetch)
//     Structure unchanged: warp = row-half, 2 px/lane, 32 edges, warp-local
//     precompute, one __syncthreads for vertex staging.
//
// Numerical contract: parity bit-identical to reference via integer-threshold
// + XOR-mask (exact-op-order division); distance path continuous => ulp-level
// error; min reassociation is exact.

namespace {

constexpr int NB  = 32;
constexpr int NP  = 32;
constexpr int NH  = 128;
constexpr int NW  = 128;
constexpr int RPB = 2;          // rows per block (2 warps per row, 4 warps)

__global__ __launch_bounds__(128) void soft_poly_kernel(
    const float* __restrict__ verts,   // (B, P, 2)
    float* __restrict__ out)           // (B, H, W)
{
    const int b    = blockIdx.y;
    const int row0 = blockIdx.x * RPB;
    const int tid  = threadIdx.x;
    const int w    = tid >> 5;         // warp 0..3
    const int lane = tid & 31;
    const int r    = w >> 1;           // local row 0..1
    const int hp   = w & 1;            // column half 0..1
    const int row  = row0 + r;
    const float gy = (float)row;

    __shared__ float  vbuf[NP * 2];    // interleaved x,y
    __shared__ float4 sA[4][NP];       // per-warp: {x1, dx*inv, ys1*dy*inv, dx}
    __shared__ float2 sB[4][NP];       // per-warp: {dy, ys1}

    if (tid < NP * 2) vbuf[tid] = verts[(size_t)b * NP * 2 + tid];
    __syncthreads();

    // ---- per-(row, edge) precompute; edge = lane; warp-local ----
    unsigned int pmA, pmB;   // parity words for this warp's 2 column groups
    {
        const int i  = lane;
        const int jp = (i + NP - 1) & (NP - 1);   // prev vertex (roll +1)
        const int kn = (i + 1) & (NP - 1);        // next vertex (roll -1)
        const float fx = vbuf[2 * i],  fy = vbuf[2 * i + 1];
        const float tx = vbuf[2 * jp], ty = vbuf[2 * jp + 1];
        const float x2 = vbuf[2 * kn], y2 = vbuf[2 * kn + 1];

        // crossing threshold, EXACT reference op order (mul, div, add)
        const bool cond = (fy > gy) != (ty > gy);
        float xint = __fadd_rn(
            __fdiv_rn(__fmul_rn(tx - fx, gy - fy), ty - fy), fx);
        if (!cond) xint = -1.0f;
        // #columns c in [0,128) with (float)c < xint — exact
        const float xc = fminf(fmaxf(ceilf(xint), 0.0f), 128.0f);
        const int ci = (int)xc - hp * 64;   // relative to this warp's half

        const int nA = min(max(ci,      0), 32);
        const int nB = min(max(ci - 32, 0), 32);
        const unsigned int mA = (unsigned int)((1ull << nA) - 1ull);
        const unsigned int mB = (unsigned int)((1ull << nB) - 1ull);
        pmA = __reduce_xor_sync(0xffffffffu, mA);
        pmB = __reduce_xor_sync(0xffffffffu, mB);

        // segment-distance constants for edge (v_i -> v_{i+1})
        const float dx = x2 - fx, dy = y2 - fy;
        const float sq  = dx * dx + dy * dy + 1e-5f;
        const float inv = __fdiv_rn(1.0f, sq);
        const float ys1 = gy - fy;
        sA[w][i] = make_float4(fx, dx * inv, ys1 * dy * inv, dx);
        sB[w][i] = make_float2(dy, ys1);
    }
    __syncwarp();   // sA/sB written and read by the same warp

    // ---- mainloop: 2 pixels per lane, 32 edges, 4 min accumulators,
    //      software-pipelined constant loads ----
    const float gx0 = (float)(hp * 64 + lane);
    const float gx1 = gx0 + 32.0f;
    float mn0a = 3.402823466e38f, mn0b = mn0a;
    float mn1a = mn0a,            mn1b = mn0a;

    float4 a  = sA[w][0];
    float2 bb = sB[w][0];

#pragma unroll
    for (int i = 0; i < NP; ++i) {
        // prefetch next iteration's constants before using this one's
        float4 an;
        float2 bn;
        if (i + 1 < NP) {
            an = sA[w][i + 1];
            bn = sB[w][i + 1];
        }

#define PIX(GX, MN) do {                                   \
        const float xs  = (GX) - a.x;                      \
        const float dot = fmaf(xs, a.y, a.z);              \
        const float t   = __saturatef(dot);                \
        const float xp  = fmaf(-t, a.w, xs);               \
        const float yp  = fmaf(-t, bb.x, bb.y);            \
        const float d   = fmaf(xp, xp, yp * yp);           \
        (MN) = fminf((MN), d);                             \
    } while (0)

        if (i & 1) {
            PIX(gx0, mn0b);
            PIX(gx1, mn1b);
        } else {
            PIX(gx0, mn0a);
            PIX(gx1, mn1a);
        }
#undef PIX

        a  = an;
        bb = bn;
    }

    const float mn0 = fminf(mn0a, mn0b);
    const float mn1 = fminf(mn1a, mn1b);

    // ---- epilogue: sign from parity, sigmoid, store ----
    float* op = out + ((size_t)b * NH + row) * NW + hp * 64 + lane;
    {
        const float io0 = ((pmA >> lane) & 1u) ? 1.0f : -1.0f;
        const float io1 = ((pmB >> lane) & 1u) ? 1.0f : -1.0f;
        const float v0  = mn0 * io0;
        const float v1  = mn1 * io1;
        op[0]  = __fdividef(1.0f, 1.0f + __expf(-v0));
        op[32] = __fdividef(1.0f, 1.0f + __expf(-v1));
    }
}

}  // namespace

extern "C" void kernel_launch(void* const* d_in, const int* in_sizes, int n_in,
                              void* d_out, int out_size) {
    const float* verts = (const float*)d_in[0];
    float* out = (float*)d_out;
    dim3 grid(NH / RPB, NB);   // 64 x 32 = 2048 blocks, 4 warps each
    soft_poly_kernel<<<grid, 128>>>(verts, out);
}

// round 10
// speedup vs baseline: 1.3392x; 1.2297x over previous
#include <cuda_runtime.h>
#include <cstdint>
#include <math.h>

// SoftPolygon B=32, P=32, 128x128.  out[b,y,x] = sigmoid(min_seg_sq * io)
//
// v10: v6 structure + warp-uniform edge culling.
//      Only edges whose AABB comes within sqrt(25)=5px of the warp's 64-px
//      row span can influence the output (sigmoid of squared distance > 25
//      saturates to 0/1 within 1.4e-11 << 1e-3 gate). Lane=edge computes a
//      conservative lower bound; ballot builds the keep mask; the mainloop
//      walks only the ~2-3 surviving edges. Parity uses ALL edges (bit-exact,
//      unchanged).
//
// Numerical contract: parity bit-identical to reference via integer-threshold
// + XOR-mask; distance path continuous (ulp error); culling affects only
// pixels where |sigmoid - {0,1}| < 1.4e-11.

namespace {

constexpr int NB  = 32;
constexpr int NP  = 32;
constexpr int NH  = 128;
constexpr int NW  = 128;
constexpr int RPB = 2;            // rows per block (2 warps per row)
constexpr float CULL_T = 25.0f;   // squared-distance saturation threshold

__global__ __launch_bounds__(128) void soft_poly_kernel(
    const float* __restrict__ verts,   // (B, P, 2)
    float* __restrict__ out)           // (B, H, W)
{
    const int b    = blockIdx.y;
    const int row0 = blockIdx.x * RPB;
    const int tid  = threadIdx.x;
    const int w    = tid >> 5;         // warp 0..3
    const int lane = tid & 31;
    const int r    = w >> 1;           // local row 0..1
    const int hp   = w & 1;            // column half 0..1
    const int row  = row0 + r;
    const float gy = (float)row;

    __shared__ float  vbuf[NP * 2];    // interleaved x,y
    __shared__ float4 sA[4][NP];       // per-warp: {x1, dx*inv, ys1*dy*inv, dx}
    __shared__ float2 sB[4][NP];       // per-warp: {dy, ys1}

    if (tid < NP * 2) vbuf[tid] = verts[(size_t)b * NP * 2 + tid];
    __syncthreads();

    // ---- per-(row, edge) precompute; edge = lane; warp-local ----
    const unsigned full = 0xffffffffu;
    unsigned int pmA, pmB;   // parity words for this warp's 2 column groups
    unsigned int bits;       // keep-mask of edges relevant to this span
    {
        const int i  = lane;
        const int jp = (i + NP - 1) & (NP - 1);   // prev vertex (roll +1)
        const int kn = (i + 1) & (NP - 1);        // next vertex (roll -1)
        const float fx = vbuf[2 * i],  fy = vbuf[2 * i + 1];
        const float tx = vbuf[2 * jp], ty = vbuf[2 * jp + 1];
        const float x2 = vbuf[2 * kn], y2 = vbuf[2 * kn + 1];

        // crossing threshold, EXACT reference op order (mul, div, add)
        const bool cond = (fy > gy) != (ty > gy);
        float xint = __fadd_rn(
            __fdiv_rn(__fmul_rn(tx - fx, gy - fy), ty - fy), fx);
        if (!cond) xint = -1.0f;
        // #columns c in [0,128) with (float)c < xint — exact
        const float xc = fminf(fmaxf(ceilf(xint), 0.0f), 128.0f);
        const int ci = (int)xc - hp * 64;   // relative to this warp's half

        const int nA = min(max(ci,      0), 32);
        const int nB = min(max(ci - 32, 0), 32);
        const unsigned int mA = (unsigned int)((1ull << nA) - 1ull);
        const unsigned int mB = (unsigned int)((1ull << nB) - 1ull);
        pmA = __reduce_xor_sync(full, mA);
        pmB = __reduce_xor_sync(full, mB);

        // segment-distance constants for edge (v_i -> v_{i+1})
        const float dx = x2 - fx, dy = y2 - fy;
        const float sq  = dx * dx + dy * dy + 1e-5f;
        const float inv = __fdiv_rn(1.0f, sq);
        const float ys1 = gy - fy;
        sA[w][i] = make_float4(fx, dx * inv, ys1 * dy * inv, dx);
        sB[w][i] = make_float2(dy, ys1);

        // conservative cull: gap between warp span [sx0, sx0+63] x {gy}
        // and edge AABB; lb^2 <= true point-to-segment dist^2 for every
        // pixel in the span.
        const float sx0 = (float)(hp * 64);
        const float sx1 = sx0 + 63.0f;
        const float eminx = fminf(fx, x2), emaxx = fmaxf(fx, x2);
        const float eminy = fminf(fy, y2), emaxy = fmaxf(fy, y2);
        const float gapx = fmaxf(0.0f, fmaxf(sx0 - emaxx, eminx - sx1));
        const float gapy = fmaxf(0.0f, fmaxf(gy  - emaxy, eminy - gy));
        const float lb2  = gapx * gapx + gapy * gapy;
        bits = __ballot_sync(full, lb2 <= CULL_T);
    }
    __syncwarp();   // sA/sB written and read by the same warp

    // ---- mainloop: only surviving edges (warp-uniform bit walk) ----
    const float gx0 = (float)(hp * 64 + lane);
    const float gx1 = gx0 + 32.0f;
    float mn0 = 3.402823466e38f, mn1 = mn0;

    while (bits) {
        const int i = __ffs(bits) - 1;
        bits &= bits - 1;
        const float4 a  = sA[w][i];
        const float2 bb = sB[w][i];

#define PIX(GX, MN) do {                                   \
        const float xs  = (GX) - a.x;                      \
        const float dot = fmaf(xs, a.y, a.z);              \
        const float t   = __saturatef(dot);                \
        const float xp  = fmaf(-t, a.w, xs);               \
        const float yp  = fmaf(-t, bb.x, bb.y);            \
        const float d   = fmaf(xp, xp, yp * yp);           \
        (MN) = fminf((MN), d);                             \
    } while (0)

        PIX(gx0, mn0);
        PIX(gx1, mn1);
#undef PIX
    }

    // ---- epilogue: sign from parity, sigmoid, store ----
    // If every edge was culled, mn stays FLT_MAX: __expf(-+FLT_MAX) -> 0/inf
    // gives exactly 1.0 / 0.0, matching the saturated reference to <1e-11.
    float* op = out + ((size_t)b * NH + row) * NW + hp * 64 + lane;
    {
        const float io0 = ((pmA >> lane) & 1u) ? 1.0f : -1.0f;
        const float io1 = ((pmB >> lane) & 1u) ? 1.0f : -1.0f;
        const float v0  = mn0 * io0;
        const float v1  = mn1 * io1;
        op[0]  = __fdividef(1.0f, 1.0f + __expf(-v0));
        op[32] = __fdividef(1.0f, 1.0f + __expf(-v1));
    }
}

}  // namespace

extern "C" void kernel_launch(void* const* d_in, const int* in_sizes, int n_in,
                              void* d_out, int out_size) {
    const float* verts = (const float*)d_in[0];
    float* out = (float*)d_out;
    dim3 grid(NH / RPB, NB);   // 64 x 32 = 2048 blocks, 4 warps each
    soft_poly_kernel<<<grid, 128>>>(verts, out);
}

// round 11
// speedup vs baseline: 1.4747x; 1.1012x over previous
#include <cuda_runtime.h>
#include <cstdint>
#include <math.h>

// SoftPolygon B=32, P=32, 128x128.  out[b,y,x] = sigmoid(min_seg_sq * io)
//
// v11: v10 + EXACT segment-segment cull (replaces loose AABB-gap bound).
//      keep(edge) <=> dist(span_segment, edge_segment) <= 5
//                 <=> segments intersect OR min of the 4 endpoint-to-segment
//                     distances <= 25   (exact identity for segment pairs)
//      Pixels lie on the span segment, so culled edges are > 5px from every
//      pixel -> sigmoid saturated within 1.4e-11. Expected kept: ~4-6 of 32
//      (vs ~12 with AABB). Parity path unchanged and bit-exact.

namespace {

constexpr int NB  = 32;
constexpr int NP  = 32;
constexpr int NH  = 128;
constexpr int NW  = 128;
constexpr int RPB = 2;            // rows per block (2 warps per row)
constexpr float CULL_T = 25.0f;   // squared-distance saturation threshold

__global__ __launch_bounds__(128) void soft_poly_kernel(
    const float* __restrict__ verts,   // (B, P, 2)
    float* __restrict__ out)           // (B, H, W)
{
    const int b    = blockIdx.y;
    const int row0 = blockIdx.x * RPB;
    const int tid  = threadIdx.x;
    const int w    = tid >> 5;         // warp 0..3
    const int lane = tid & 31;
    const int r    = w >> 1;           // local row 0..1
    const int hp   = w & 1;            // column half 0..1
    const int row  = row0 + r;
    const float gy = (float)row;

    __shared__ float  vbuf[NP * 2];    // interleaved x,y
    __shared__ float4 sA[4][NP];       // per-warp: {x1, dx*inv, ys1*dy*inv, dx}
    __shared__ float2 sB[4][NP];       // per-warp: {dy, ys1}

    if (tid < NP * 2) vbuf[tid] = verts[(size_t)b * NP * 2 + tid];
    __syncthreads();

    // ---- per-(row, edge) precompute; edge = lane; warp-local ----
    const unsigned full = 0xffffffffu;
    unsigned int pmA, pmB;   // parity words for this warp's 2 column groups
    unsigned int bits;       // keep-mask of edges relevant to this span
    {
        const int i  = lane;
        const int jp = (i + NP - 1) & (NP - 1);   // prev vertex (roll +1)
        const int kn = (i + 1) & (NP - 1);        // next vertex (roll -1)
        const float fx = vbuf[2 * i],  fy = vbuf[2 * i + 1];
        const float tx = vbuf[2 * jp], ty = vbuf[2 * jp + 1];
        const float x2 = vbuf[2 * kn], y2 = vbuf[2 * kn + 1];

        // crossing threshold, EXACT reference op order (mul, div, add)
        const bool cond = (fy > gy) != (ty > gy);
        float xint = __fadd_rn(
            __fdiv_rn(__fmul_rn(tx - fx, gy - fy), ty - fy), fx);
        if (!cond) xint = -1.0f;
        // #columns c in [0,128) with (float)c < xint — exact
        const float xc = fminf(fmaxf(ceilf(xint), 0.0f), 128.0f);
        const int ci = (int)xc - hp * 64;   // relative to this warp's half

        const int nA = min(max(ci,      0), 32);
        const int nB = min(max(ci - 32, 0), 32);
        const unsigned int mA = (unsigned int)((1ull << nA) - 1ull);
        const unsigned int mB = (unsigned int)((1ull << nB) - 1ull);
        pmA = __reduce_xor_sync(full, mA);
        pmB = __reduce_xor_sync(full, mB);

        // segment-distance constants for edge (v_i -> v_{i+1})
        const float dx = x2 - fx, dy = y2 - fy;
        const float sq  = dx * dx + dy * dy + 1e-5f;
        const float inv = __fdiv_rn(1.0f, sq);
        const float ys1 = gy - fy;
        const float ys2 = gy - y2;
        sA[w][i] = make_float4(fx, dx * inv, ys1 * dy * inv, dx);
        sB[w][i] = make_float2(dy, ys1);

        // ---- EXACT cull: dist(span segment, edge segment)^2 <= 25 ----
        const float sxa = (float)(hp * 64);
        const float sxb = sxa + 63.0f;

        // (1) edge endpoints -> span (horizontal segment at y=gy)
        const float ga  = fmaxf(0.0f, fmaxf(sxa - fx, fx - sxb));
        const float gb  = fmaxf(0.0f, fmaxf(sxa - x2, x2 - sxb));
        const float dva = fmaf(ga, ga, ys1 * ys1);
        const float dvb = fmaf(gb, gb, ys2 * ys2);

        // (2) span endpoints -> edge (point-to-segment)
        float dpa, dpb;
        {
            const float xsA = sxa - fx;
            const float tA  = __saturatef((xsA * dx + ys1 * dy) * inv);
            const float xpA = fmaf(-tA, dx, xsA);
            const float ypA = fmaf(-tA, dy, ys1);
            dpa = fmaf(xpA, xpA, ypA * ypA);
            const float xsB = sxb - fx;
            const float tB  = __saturatef((xsB * dx + ys1 * dy) * inv);
            const float xpB = fmaf(-tB, dx, xsB);
            const float ypB = fmaf(-tB, dy, ys1);
            dpb = fmaf(xpB, xpB, ypB * ypB);
        }

        // (3) proper intersection of edge with the span segment
        //     (colinear/touching cases are covered by endpoint distances)
        const bool crossesLine = (fy > gy) != (y2 > gy);
        const float u  = fmaf(fx, dy, dx * ys1);     // x_cross * dy
        const bool xin = ((u - sxa * dy) * dy >= 0.0f) &&
                         ((sxb * dy - u) * dy >= 0.0f);
        const bool isect = crossesLine && xin;

        const float best = fminf(fminf(dva, dvb), fminf(dpa, dpb));
        bits = __ballot_sync(full, isect || (best <= CULL_T));
    }
    __syncwarp();   // sA/sB written and read by the same warp

    // ---- mainloop: only surviving edges (warp-uniform bit walk) ----
    const float gx0 = (float)(hp * 64 + lane);
    const float gx1 = gx0 + 32.0f;
    float mn0 = 3.402823466e38f, mn1 = mn0;

    while (bits) {
        const int i = __ffs(bits) - 1;
        bits &= bits - 1;
        const float4 a  = sA[w][i];
        const float2 bb = sB[w][i];

#define PIX(GX, MN) do {                                   \
        const float xs  = (GX) - a.x;                      \
        const float dot = fmaf(xs, a.y, a.z);              \
        const float t   = __saturatef(dot);                \
        const float xp  = fmaf(-t, a.w, xs);               \
        const float yp  = fmaf(-t, bb.x, bb.y);            \
        const float d   = fmaf(xp, xp, yp * yp);           \
        (MN) = fminf((MN), d);                             \
    } while (0)

        PIX(gx0, mn0);
        PIX(gx1, mn1);
#undef PIX
    }

    // ---- epilogue: sign from parity, sigmoid, store ----
    // All-culled => mn stays FLT_MAX => exact 0/1, matching saturation.
    float* op = out + ((size_t)b * NH + row) * NW + hp * 64 + lane;
    {
        const float io0 = ((pmA >> lane) & 1u) ? 1.0f : -1.0f;
        const float io1 = ((pmB >> lane) & 1u) ? 1.0f : -1.0f;
        const float v0  = mn0 * io0;
        const float v1  = mn1 * io1;
        op[0]  = __fdividef(1.0f, 1.0f + __expf(-v0));
        op[32] = __fdividef(1.0f, 1.0f + __expf(-v1));
    }
}

}  // namespace

extern "C" void kernel_launch(void* const* d_in, const int* in_sizes, int n_in,
                              void* d_out, int out_size) {
    const float* verts = (const float*)d_in[0];
    float* out = (float*)d_out;
    dim3 grid(NH / RPB, NB);   // 64 x 32 = 2048 blocks, 4 warps each
    soft_poly_kernel<<<grid, 128>>>(verts, out);
}